// round 11
// baseline (speedup 1.0000x reference)
#include <cuda_runtime.h>
#include <math.h>

#define SEQ 512   // hidden dim of h
#define EMB 512   // embedding dim
#define DD  384   // vfeat channels
#define LL  384   // vfeat regions

#define NP1 6     // split-K partials for GEMM1 (K=384, slab 64)
#define NP2 8     // split-K partials for GEMM2 (K=512, slab 64)

// Scratch (device globals — no allocation allowed in kernel_launch)
__device__ float g_gh[EMB];               // wg @ h
__device__ float g_spart[NP1][EMB * LL];  // split-K partials of s = wv@v (+bias in part 0)
__device__ float g_zpart[NP2][LL * LL];   // split-K partials of z = wh@tanh(s)
__device__ float g_alpha[LL * LL];        // softmax rows (384,384)

__device__ __forceinline__ void pdl_trigger() {
    asm volatile("griddepcontrol.launch_dependents;");
}

// ---------------------------------------------------------------------------
// gh[row] = dot(wg[row,:], h). One warp per row, 64 blocks — spreads the
// 16K wg loads chip-wide (R10 showed fusing this into GEMM1 serializes them).
// ---------------------------------------------------------------------------
__global__ void __launch_bounds__(256) k_gh(const float* __restrict__ wg,
                                            const float* __restrict__ h) {
    pdl_trigger();   // let GEMM1 launch & stage its tiles immediately
    int w = (blockIdx.x * 256 + threadIdx.x) >> 5;   // 0..511
    int lane = threadIdx.x & 31;
    const float4* wr = (const float4*)(wg + w * SEQ);
    const float4* hr = (const float4*)h;
    float p = 0.f;
    #pragma unroll
    for (int c = 0; c < 4; c++) {
        float4 a = wr[lane + 32 * c], b = hr[lane + 32 * c];
        p += a.x * b.x + a.y * b.y + a.z * b.z + a.w * b.w;
    }
    #pragma unroll
    for (int o = 16; o; o >>= 1) p += __shfl_down_sync(0xffffffffu, p, o);
    if (lane == 0) g_gh[w] = p;
}

// ---------------------------------------------------------------------------
// GEMM1 split-K6: g_spart[kc] = wv[:, kc*64:+64] @ v[kc*64:+64, :]
// 128x64 block tile, 64-deep slab staged once, 8x4 per thread.
// kc==0 adds bias g_gh[m] (after gridsync). Grid (6,4,6) = 144 blocks (1/SM).
// ---------------------------------------------------------------------------
__global__ void __launch_bounds__(256) k_gemm1(const float* __restrict__ wv,
                                               const float* __restrict__ v) {
    constexpr int KS = 64;
    __shared__ float As[KS][132];   // As[k][m]
    __shared__ float Bs[KS][68];

    const int tx = threadIdx.x;
    const int tn = tx & 15;
    const int tm = tx >> 4;
    const int bn = blockIdx.x, bm = blockIdx.y, kc = blockIdx.z;
    const int kbase = kc * KS;

    pdl_trigger();   // GEMM2 may launch and stage wh under our mainloop

    // A tile: wv rows bm*128..+127, cols kbase..+63 -> transposed As[k][m]
    {
        int m = tx >> 1, c0 = (tx & 1) * 32;
        const float* ap = wv + (bm * 128 + m) * DD + kbase + c0;
        #pragma unroll
        for (int q = 0; q < 8; q++) {
            float4 a = *(const float4*)(ap + 4 * q);
            As[c0 + 4 * q + 0][m] = a.x; As[c0 + 4 * q + 1][m] = a.y;
            As[c0 + 4 * q + 2][m] = a.z; As[c0 + 4 * q + 3][m] = a.w;
        }
    }
    // B tile: v rows kbase..+63, cols bn*64..+63
    #pragma unroll
    for (int q = 0; q < 4; q++) {
        int e = tx + 256 * q;
        int k = e >> 4, n4 = (e & 15) * 4;
        *(float4*)&Bs[k][n4] = *(const float4*)&v[(kbase + k) * LL + bn * 64 + n4];
    }
    __syncthreads();

    float acc[8][4] = {};
    #pragma unroll 8
    for (int k = 0; k < KS; k++) {
        float4 a0 = *(const float4*)&As[k][tm * 8];
        float4 a1 = *(const float4*)&As[k][tm * 8 + 4];
        float4 b  = *(const float4*)&Bs[k][tn * 4];
        float av[8] = {a0.x, a0.y, a0.z, a0.w, a1.x, a1.y, a1.z, a1.w};
        float bv[4] = {b.x, b.y, b.z, b.w};
        #pragma unroll
        for (int i = 0; i < 8; i++)
            #pragma unroll
            for (int j = 0; j < 4; j++)
                acc[i][j] += av[i] * bv[j];
    }

    cudaGridDependencySynchronize();   // g_gh ready (k_gh overlapped)

    float* outp = g_spart[kc];
    #pragma unroll
    for (int i = 0; i < 8; i++) {
        int m = bm * 128 + tm * 8 + i;
        float bias = (kc == 0) ? g_gh[m] : 0.f;
        float4 r;
        r.x = acc[i][0] + bias; r.y = acc[i][1] + bias;
        r.z = acc[i][2] + bias; r.w = acc[i][3] + bias;
        *(float4*)&outp[m * LL + bn * 64 + tn * 4] = r;
    }
}

// ---------------------------------------------------------------------------
// GEMM2 split-K8: g_zpart[kc] = wh[:, kc*64:+64] @ tanh(s)[kc*64:+64, :]
// A (wh) staged BEFORE gridsync (true overlap now that GEMM1 triggers early);
// B = tanh(sum of 6 s-partials) on the fly. Grid (6,3,8) = 144 blocks.
// ---------------------------------------------------------------------------
__global__ void __launch_bounds__(256) k_gemm2(const float* __restrict__ wh) {
    constexpr int KS = 64;
    __shared__ float As[KS][132];
    __shared__ float Bs[KS][68];

    const int tx = threadIdx.x;
    const int tn = tx & 15;
    const int tm = tx >> 4;
    const int bn = blockIdx.x, bm = blockIdx.y, kc = blockIdx.z;
    const int kbase = kc * KS;

    pdl_trigger();   // softmax may launch (it sleeps at its gridsync)

    // A tile: wh rows bm*128..+127, cols kbase..+63 (independent of GEMM1)
    {
        int m = tx >> 1, c0 = (tx & 1) * 32;
        const float* ap = wh + (bm * 128 + m) * EMB + kbase + c0;
        #pragma unroll
        for (int q = 0; q < 8; q++) {
            float4 a = *(const float4*)(ap + 4 * q);
            As[c0 + 4 * q + 0][m] = a.x; As[c0 + 4 * q + 1][m] = a.y;
            As[c0 + 4 * q + 2][m] = a.z; As[c0 + 4 * q + 3][m] = a.w;
        }
    }

    cudaGridDependencySynchronize();   // s-partials ready

    // B tile: ts rows kbase..+63, cols bn*64..+63 = tanh(sum of NP1 partials)
    #pragma unroll
    for (int q = 0; q < 4; q++) {
        int e = tx + 256 * q;
        int k = e >> 4, n4 = (e & 15) * 4;
        int off = (kbase + k) * LL + bn * 64 + n4;
        float4 s = *(const float4*)&g_spart[0][off];
        #pragma unroll
        for (int p = 1; p < NP1; p++) {
            float4 t = *(const float4*)&g_spart[p][off];
            s.x += t.x; s.y += t.y; s.z += t.z; s.w += t.w;
        }
        float4 b;
        b.x = tanhf(s.x); b.y = tanhf(s.y); b.z = tanhf(s.z); b.w = tanhf(s.w);
        *(float4*)&Bs[k][n4] = b;
    }
    __syncthreads();

    float acc[8][4] = {};
    #pragma unroll 8
    for (int k = 0; k < KS; k++) {
        float4 a0 = *(const float4*)&As[k][tm * 8];
        float4 a1 = *(const float4*)&As[k][tm * 8 + 4];
        float4 b  = *(const float4*)&Bs[k][tn * 4];
        float av[8] = {a0.x, a0.y, a0.z, a0.w, a1.x, a1.y, a1.z, a1.w};
        float bv[4] = {b.x, b.y, b.z, b.w};
        #pragma unroll
        for (int i = 0; i < 8; i++)
            #pragma unroll
            for (int j = 0; j < 4; j++)
                acc[i][j] += av[i] * bv[j];
    }

    float* outp = g_zpart[kc];
    #pragma unroll
    for (int i = 0; i < 8; i++) {
        int m = bm * 128 + tm * 8 + i;
        float4 r;
        r.x = acc[i][0]; r.y = acc[i][1]; r.z = acc[i][2]; r.w = acc[i][3];
        *(float4*)&outp[m * LL + bn * 64 + tn * 4] = r;
    }
}

// ---------------------------------------------------------------------------
// Row softmax over z = sum of NP2 partials. One block per row,
// 128 threads (96 active), MLP=NP2 independent partial loads.
// ---------------------------------------------------------------------------
__global__ void __launch_bounds__(128) k_softmax() {
    pdl_trigger();   // k_out may launch and preload v into registers
    cudaGridDependencySynchronize();

    const int row = blockIdx.x;            // 0..383
    const int t = threadIdx.x;             // 0..127 (96 active for data)
    const int lane = t & 31, w = t >> 5;

    __shared__ float sred[4];
    __shared__ float ssum[4];

    float4 x;
    const int idx = row * 96 + (t < 96 ? t : 95);
    {
        float4 s = ((const float4*)g_zpart[0])[idx];
        #pragma unroll
        for (int p = 1; p < NP2; p++) {
            float4 q = ((const float4*)g_zpart[p])[idx];
            s.x += q.x; s.y += q.y; s.z += q.z; s.w += q.w;
        }
        x = s;
    }

    float m = fmaxf(fmaxf(x.x, x.y), fmaxf(x.z, x.w));
    if (t >= 96) m = -1e30f;
    #pragma unroll
    for (int o = 16; o; o >>= 1) m = fmaxf(m, __shfl_xor_sync(0xffffffffu, m, o));
    if (lane == 0) sred[w] = m;
    __syncthreads();
    m = fmaxf(fmaxf(sred[0], sred[1]), fmaxf(sred[2], sred[3]));

    x.x = __expf(x.x - m); x.y = __expf(x.y - m);
    x.z = __expf(x.z - m); x.w = __expf(x.w - m);
    float s = (x.x + x.y) + (x.z + x.w);
    if (t >= 96) s = 0.f;
    #pragma unroll
    for (int o = 16; o; o >>= 1) s += __shfl_xor_sync(0xffffffffu, s, o);
    if (lane == 0) ssum[w] = s;
    __syncthreads();
    float inv = 1.f / (((ssum[0] + ssum[1]) + (ssum[2] + ssum[3])));

    if (t < 96) {
        x.x *= inv; x.y *= inv; x.z *= inv; x.w *= inv;
        ((float4*)g_alpha)[idx] = x;
    }
}

// ---------------------------------------------------------------------------
// out[i,j,k] = v[j,k] * alpha[i,j].  v loads issued BEFORE gridsync (now
// genuinely overlapped with softmax). At write roofline — core unchanged (R9).
// ---------------------------------------------------------------------------
__global__ void __launch_bounds__(384) k_out(const float* __restrict__ v,
                                             float4* __restrict__ out) {
    const int jb = blockIdx.x;    // 0..11
    const int ic = blockIdx.y;    // 0..23
    const int t  = threadIdx.x;   // 0..383

    const int g  = t / 96;
    const int k4 = t % 96;

    __shared__ float sa[16][32];

    float4 vv[8];
    #pragma unroll
    for (int jlo = 0; jlo < 8; jlo++)
        vv[jlo] = ((const float4*)v)[(jb * 32 + jlo * 4 + g) * 96 + k4];

    cudaGridDependencySynchronize();   // alpha ready

    #pragma unroll
    for (int idx = t; idx < 512; idx += 384) {
        int r = idx >> 5, c = idx & 31;
        sa[r][c] = g_alpha[(ic * 16 + r) * LL + jb * 32 + c];
    }
    __syncthreads();

    #pragma unroll 2
    for (int il = 0; il < 16; il++) {
        float4* o = out + ((size_t)(ic * 16 + il) * LL + jb * 32) * 96 + g * 96 + k4;
        #pragma unroll
        for (int jlo = 0; jlo < 8; jlo++) {
            float a = sa[il][jlo * 4 + g];
            float4 r;
            r.x = vv[jlo].x * a; r.y = vv[jlo].y * a;
            r.z = vv[jlo].z * a; r.w = vv[jlo].w * a;
            __stcs(o + jlo * 4 * 96, r);
        }
    }
}

// ---------------------------------------------------------------------------
template <typename F, typename... Args>
static void pdl_launch(F kern, dim3 g, dim3 b, Args... args) {
    cudaLaunchConfig_t cfg = {};
    cfg.gridDim = g; cfg.blockDim = b;
    cfg.dynamicSmemBytes = 0; cfg.stream = 0;
    cudaLaunchAttribute at;
    at.id = cudaLaunchAttributeProgrammaticStreamSerialization;
    at.val.programmaticStreamSerializationAllowed = 1;
    cfg.attrs = &at; cfg.numAttrs = 1;
    cudaLaunchKernelEx(&cfg, kern, args...);
}

extern "C" void kernel_launch(void* const* d_in, const int* in_sizes, int n_in,
                              void* d_out, int out_size) {
    const float* h  = (const float*)d_in[0];   // (512,1)
    const float* v  = (const float*)d_in[1];   // (384,384)
    const float* wh = (const float*)d_in[2];   // (384,512)
    const float* wv = (const float*)d_in[3];   // (512,384)
    const float* wg = (const float*)d_in[4];   // (512,512)

    k_gh<<<64, 256>>>(wg, h);

    pdl_launch(k_gemm1, dim3(LL / 64, EMB / 128, NP1), dim3(256), wv, v);
    pdl_launch(k_gemm2, dim3(LL / 64, LL / 128, NP2), dim3(256), wh);
    pdl_launch(k_softmax, dim3(LL), dim3(128));
    pdl_launch(k_out, dim3(12, 24), dim3(384), v, (float4*)d_out);

    (void)in_sizes; (void)n_in; (void)out_size;
}

// round 12
// speedup vs baseline: 1.1021x; 1.1021x over previous
#include <cuda_runtime.h>
#include <math.h>

#define SEQ 512   // hidden dim of h
#define EMB 512   // embedding dim
#define DD  384   // vfeat channels
#define LL  384   // vfeat regions

#define NP1 6     // split-K partials for GEMM1 (K=384, slab 64)
#define NP2 8     // split-K partials for GEMM2 (K=512, slab 64)

// Scratch (device globals — no allocation allowed in kernel_launch)
__device__ float g_gh[EMB];               // wg @ h
__device__ float g_spart[NP1][EMB * LL];  // split-K partials of s = wv@v (+bias in part 0)
__device__ float g_zpart[NP2][LL * LL];   // split-K partials of z = wh@tanh(s)
__device__ float g_alpha[LL * LL];        // softmax rows (384,384)

// ---------------------------------------------------------------------------
// gh[row] = dot(wg[row,:], h). One warp per row, 64 blocks — spreads the
// 16K wg loads chip-wide (R10 showed fusing this into GEMM1 serializes them).
// ---------------------------------------------------------------------------
__global__ void __launch_bounds__(256) k_gh(const float* __restrict__ wg,
                                            const float* __restrict__ h) {
    int w = (blockIdx.x * 256 + threadIdx.x) >> 5;   // 0..511
    int lane = threadIdx.x & 31;
    const float4* wr = (const float4*)(wg + w * SEQ);
    const float4* hr = (const float4*)h;
    float p = 0.f;
    #pragma unroll
    for (int c = 0; c < 4; c++) {
        float4 a = wr[lane + 32 * c], b = hr[lane + 32 * c];
        p += a.x * b.x + a.y * b.y + a.z * b.z + a.w * b.w;
    }
    #pragma unroll
    for (int o = 16; o; o >>= 1) p += __shfl_down_sync(0xffffffffu, p, o);
    if (lane == 0) g_gh[w] = p;
}

// ---------------------------------------------------------------------------
// GEMM1 split-K6: g_spart[kc] = wv[:, kc*64:+64] @ v[kc*64:+64, :]
// 128x64 block tile, 64-deep slab staged once, 8x4 per thread.
// kc==0 adds bias g_gh[m] (after gridsync). Grid (6,4,6) = 144 blocks (1/SM).
// ---------------------------------------------------------------------------
__global__ void __launch_bounds__(256) k_gemm1(const float* __restrict__ wv,
                                               const float* __restrict__ v) {
    constexpr int KS = 64;
    __shared__ float As[KS][132];   // As[k][m]
    __shared__ float Bs[KS][68];

    const int tx = threadIdx.x;
    const int tn = tx & 15;
    const int tm = tx >> 4;
    const int bn = blockIdx.x, bm = blockIdx.y, kc = blockIdx.z;
    const int kbase = kc * KS;

    // A tile: wv rows bm*128..+127, cols kbase..+63 -> transposed As[k][m]
    {
        int m = tx >> 1, c0 = (tx & 1) * 32;
        const float* ap = wv + (bm * 128 + m) * DD + kbase + c0;
        #pragma unroll
        for (int q = 0; q < 8; q++) {
            float4 a = *(const float4*)(ap + 4 * q);
            As[c0 + 4 * q + 0][m] = a.x; As[c0 + 4 * q + 1][m] = a.y;
            As[c0 + 4 * q + 2][m] = a.z; As[c0 + 4 * q + 3][m] = a.w;
        }
    }
    // B tile: v rows kbase..+63, cols bn*64..+63
    #pragma unroll
    for (int q = 0; q < 4; q++) {
        int e = tx + 256 * q;
        int k = e >> 4, n4 = (e & 15) * 4;
        *(float4*)&Bs[k][n4] = *(const float4*)&v[(kbase + k) * LL + bn * 64 + n4];
    }
    __syncthreads();

    float acc[8][4] = {};
    #pragma unroll 8
    for (int k = 0; k < KS; k++) {
        float4 a0 = *(const float4*)&As[k][tm * 8];
        float4 a1 = *(const float4*)&As[k][tm * 8 + 4];
        float4 b  = *(const float4*)&Bs[k][tn * 4];
        float av[8] = {a0.x, a0.y, a0.z, a0.w, a1.x, a1.y, a1.z, a1.w};
        float bv[4] = {b.x, b.y, b.z, b.w};
        #pragma unroll
        for (int i = 0; i < 8; i++)
            #pragma unroll
            for (int j = 0; j < 4; j++)
                acc[i][j] += av[i] * bv[j];
    }

    cudaGridDependencySynchronize();   // g_gh ready (k_gh overlapped)

    float* outp = g_spart[kc];
    #pragma unroll
    for (int i = 0; i < 8; i++) {
        int m = bm * 128 + tm * 8 + i;
        float bias = (kc == 0) ? g_gh[m] : 0.f;
        float4 r;
        r.x = acc[i][0] + bias; r.y = acc[i][1] + bias;
        r.z = acc[i][2] + bias; r.w = acc[i][3] + bias;
        *(float4*)&outp[m * LL + bn * 64 + tn * 4] = r;
    }
}

// ---------------------------------------------------------------------------
// GEMM2 split-K8: g_zpart[kc] = wh[:, kc*64:+64] @ tanh(s)[kc*64:+64, :]
// A (wh) staged BEFORE gridsync; B = tanh(sum of 6 s-partials) on the fly.
// Grid (6,3,8) = 144 blocks.
// ---------------------------------------------------------------------------
__global__ void __launch_bounds__(256) k_gemm2(const float* __restrict__ wh) {
    constexpr int KS = 64;
    __shared__ float As[KS][132];
    __shared__ float Bs[KS][68];

    const int tx = threadIdx.x;
    const int tn = tx & 15;
    const int tm = tx >> 4;
    const int bn = blockIdx.x, bm = blockIdx.y, kc = blockIdx.z;
    const int kbase = kc * KS;

    // A tile: wh rows bm*128..+127, cols kbase..+63 (independent of GEMM1)
    {
        int m = tx >> 1, c0 = (tx & 1) * 32;
        const float* ap = wh + (bm * 128 + m) * EMB + kbase + c0;
        #pragma unroll
        for (int q = 0; q < 8; q++) {
            float4 a = *(const float4*)(ap + 4 * q);
            As[c0 + 4 * q + 0][m] = a.x; As[c0 + 4 * q + 1][m] = a.y;
            As[c0 + 4 * q + 2][m] = a.z; As[c0 + 4 * q + 3][m] = a.w;
        }
    }

    cudaGridDependencySynchronize();   // s-partials ready

    // B tile: ts rows kbase..+63, cols bn*64..+63 = tanh(sum of NP1 partials)
    #pragma unroll
    for (int q = 0; q < 4; q++) {
        int e = tx + 256 * q;
        int k = e >> 4, n4 = (e & 15) * 4;
        int off = (kbase + k) * LL + bn * 64 + n4;
        float4 s = *(const float4*)&g_spart[0][off];
        #pragma unroll
        for (int p = 1; p < NP1; p++) {
            float4 t = *(const float4*)&g_spart[p][off];
            s.x += t.x; s.y += t.y; s.z += t.z; s.w += t.w;
        }
        float4 b;
        b.x = tanhf(s.x); b.y = tanhf(s.y); b.z = tanhf(s.z); b.w = tanhf(s.w);
        *(float4*)&Bs[k][n4] = b;
    }
    __syncthreads();

    float acc[8][4] = {};
    #pragma unroll 8
    for (int k = 0; k < KS; k++) {
        float4 a0 = *(const float4*)&As[k][tm * 8];
        float4 a1 = *(const float4*)&As[k][tm * 8 + 4];
        float4 b  = *(const float4*)&Bs[k][tn * 4];
        float av[8] = {a0.x, a0.y, a0.z, a0.w, a1.x, a1.y, a1.z, a1.w};
        float bv[4] = {b.x, b.y, b.z, b.w};
        #pragma unroll
        for (int i = 0; i < 8; i++)
            #pragma unroll
            for (int j = 0; j < 4; j++)
                acc[i][j] += av[i] * bv[j];
    }

    float* outp = g_zpart[kc];
    #pragma unroll
    for (int i = 0; i < 8; i++) {
        int m = bm * 128 + tm * 8 + i;
        float4 r;
        r.x = acc[i][0]; r.y = acc[i][1]; r.z = acc[i][2]; r.w = acc[i][3];
        *(float4*)&outp[m * LL + bn * 64 + tn * 4] = r;
    }
}

// ---------------------------------------------------------------------------
// Row softmax over z = sum of NP2 partials. One block per row, 96 threads,
// MLP=NP2 independent partial loads, 2-level (shuffle + 3-word) reduction.
// ---------------------------------------------------------------------------
__global__ void __launch_bounds__(96) k_softmax() {
    cudaGridDependencySynchronize();

    const int row = blockIdx.x;            // 0..383
    const int t = threadIdx.x;             // 0..95
    const int lane = t & 31, w = t >> 5;

    __shared__ float sred[3];
    __shared__ float ssum[3];

    const int idx = row * 96 + t;
    float4 x = ((const float4*)g_zpart[0])[idx];
    #pragma unroll
    for (int p = 1; p < NP2; p++) {
        float4 q = ((const float4*)g_zpart[p])[idx];
        x.x += q.x; x.y += q.y; x.z += q.z; x.w += q.w;
    }

    float m = fmaxf(fmaxf(x.x, x.y), fmaxf(x.z, x.w));
    #pragma unroll
    for (int o = 16; o; o >>= 1) m = fmaxf(m, __shfl_xor_sync(0xffffffffu, m, o));
    if (lane == 0) sred[w] = m;
    __syncthreads();
    m = fmaxf(fmaxf(sred[0], sred[1]), sred[2]);

    x.x = __expf(x.x - m); x.y = __expf(x.y - m);
    x.z = __expf(x.z - m); x.w = __expf(x.w - m);
    float s = (x.x + x.y) + (x.z + x.w);
    #pragma unroll
    for (int o = 16; o; o >>= 1) s += __shfl_xor_sync(0xffffffffu, s, o);
    if (lane == 0) ssum[w] = s;
    __syncthreads();
    float inv = 1.f / (ssum[0] + ssum[1] + ssum[2]);

    x.x *= inv; x.y *= inv; x.z *= inv; x.w *= inv;
    ((float4*)g_alpha)[idx] = x;
}

// ---------------------------------------------------------------------------
// out[i,j,k] = v[j,k] * alpha[i,j].  v loads issued BEFORE gridsync.
// At write roofline — unchanged from R9.
// ---------------------------------------------------------------------------
__global__ void __launch_bounds__(384) k_out(const float* __restrict__ v,
                                             float4* __restrict__ out) {
    const int jb = blockIdx.x;    // 0..11
    const int ic = blockIdx.y;    // 0..23
    const int t  = threadIdx.x;   // 0..383

    const int g  = t / 96;
    const int k4 = t % 96;

    __shared__ float sa[16][32];

    float4 vv[8];
    #pragma unroll
    for (int jlo = 0; jlo < 8; jlo++)
        vv[jlo] = ((const float4*)v)[(jb * 32 + jlo * 4 + g) * 96 + k4];

    cudaGridDependencySynchronize();   // alpha ready

    #pragma unroll
    for (int idx = t; idx < 512; idx += 384) {
        int r = idx >> 5, c = idx & 31;
        sa[r][c] = g_alpha[(ic * 16 + r) * LL + jb * 32 + c];
    }
    __syncthreads();

    #pragma unroll 2
    for (int il = 0; il < 16; il++) {
        float4* o = out + ((size_t)(ic * 16 + il) * LL + jb * 32) * 96 + g * 96 + k4;
        #pragma unroll
        for (int jlo = 0; jlo < 8; jlo++) {
            float a = sa[il][jlo * 4 + g];
            float4 r;
            r.x = vv[jlo].x * a; r.y = vv[jlo].y * a;
            r.z = vv[jlo].z * a; r.w = vv[jlo].w * a;
            __stcs(o + jlo * 4 * 96, r);
        }
    }
}

// ---------------------------------------------------------------------------
template <typename F, typename... Args>
static void pdl_launch(F kern, dim3 g, dim3 b, Args... args) {
    cudaLaunchConfig_t cfg = {};
    cfg.gridDim = g; cfg.blockDim = b;
    cfg.dynamicSmemBytes = 0; cfg.stream = 0;
    cudaLaunchAttribute at;
    at.id = cudaLaunchAttributeProgrammaticStreamSerialization;
    at.val.programmaticStreamSerializationAllowed = 1;
    cfg.attrs = &at; cfg.numAttrs = 1;
    cudaLaunchKernelEx(&cfg, kern, args...);
}

extern "C" void kernel_launch(void* const* d_in, const int* in_sizes, int n_in,
                              void* d_out, int out_size) {
    const float* h  = (const float*)d_in[0];   // (512,1)
    const float* v  = (const float*)d_in[1];   // (384,384)
    const float* wh = (const float*)d_in[2];   // (384,512)
    const float* wv = (const float*)d_in[3];   // (512,384)
    const float* wg = (const float*)d_in[4];   // (512,512)

    k_gh<<<64, 256>>>(wg, h);

    pdl_launch(k_gemm1, dim3(LL / 64, EMB / 128, NP1), dim3(256), wv, v);
    pdl_launch(k_gemm2, dim3(LL / 64, LL / 128, NP2), dim3(256), wh);
    pdl_launch(k_softmax, dim3(LL), dim3(96));
    pdl_launch(k_out, dim3(12, 24), dim3(384), v, (float4*)d_out);

    (void)in_sizes; (void)n_in; (void)out_size;
}

// round 13
// speedup vs baseline: 1.1441x; 1.0381x over previous
#include <cuda_runtime.h>
#include <math.h>

#define SEQ 512   // hidden dim of h
#define EMB 512   // embedding dim
#define DD  384   // vfeat channels
#define LL  384   // vfeat regions

#define NP1 6     // split-K partials for GEMM1 (K=384, slab 64)
#define NP2 8     // split-K partials for GEMM2 (K=512, slab 64)

// Scratch (device globals — no allocation allowed in kernel_launch)
__device__ float g_spart[NP1][EMB * LL];  // split-K partials of s = wv@v (bias added in GEMM2)
__device__ float g_zpart[NP2][LL * LL];   // split-K partials of z = wh@tanh(s+gh)
__device__ float g_alpha[LL * LL];        // softmax rows (384,384)

// ---------------------------------------------------------------------------
// GEMM1 split-K6: g_spart[kc] = wv[:, kc*64:+64] @ v[kc*64:+64, :]
// 128x64 block tile, 64-deep slab staged once, 8x4 per thread.
// NO dependencies, NO gridsync, NO bias (bias folded into GEMM2's B build).
// Grid (6,4,6) = 144 blocks (1/SM).
// ---------------------------------------------------------------------------
__global__ void __launch_bounds__(256) k_gemm1(const float* __restrict__ wv,
                                               const float* __restrict__ v) {
    constexpr int KS = 64;
    __shared__ float As[KS][132];   // As[k][m]
    __shared__ float Bs[KS][68];

    const int tx = threadIdx.x;
    const int tn = tx & 15;
    const int tm = tx >> 4;
    const int bn = blockIdx.x, bm = blockIdx.y, kc = blockIdx.z;
    const int kbase = kc * KS;

    // A tile: wv rows bm*128..+127, cols kbase..+63 -> transposed As[k][m]
    {
        int m = tx >> 1, c0 = (tx & 1) * 32;
        const float* ap = wv + (bm * 128 + m) * DD + kbase + c0;
        #pragma unroll
        for (int q = 0; q < 8; q++) {
            float4 a = *(const float4*)(ap + 4 * q);
            As[c0 + 4 * q + 0][m] = a.x; As[c0 + 4 * q + 1][m] = a.y;
            As[c0 + 4 * q + 2][m] = a.z; As[c0 + 4 * q + 3][m] = a.w;
        }
    }
    // B tile: v rows kbase..+63, cols bn*64..+63
    #pragma unroll
    for (int q = 0; q < 4; q++) {
        int e = tx + 256 * q;
        int k = e >> 4, n4 = (e & 15) * 4;
        *(float4*)&Bs[k][n4] = *(const float4*)&v[(kbase + k) * LL + bn * 64 + n4];
    }
    __syncthreads();

    float acc[8][4] = {};
    #pragma unroll 8
    for (int k = 0; k < KS; k++) {
        float4 a0 = *(const float4*)&As[k][tm * 8];
        float4 a1 = *(const float4*)&As[k][tm * 8 + 4];
        float4 b  = *(const float4*)&Bs[k][tn * 4];
        float av[8] = {a0.x, a0.y, a0.z, a0.w, a1.x, a1.y, a1.z, a1.w};
        float bv[4] = {b.x, b.y, b.z, b.w};
        #pragma unroll
        for (int i = 0; i < 8; i++)
            #pragma unroll
            for (int j = 0; j < 4; j++)
                acc[i][j] += av[i] * bv[j];
    }

    float* outp = g_spart[kc];
    #pragma unroll
    for (int i = 0; i < 8; i++) {
        int m = bm * 128 + tm * 8 + i;
        float4 r;
        r.x = acc[i][0]; r.y = acc[i][1]; r.z = acc[i][2]; r.w = acc[i][3];
        *(float4*)&outp[m * LL + bn * 64 + tn * 4] = r;
    }
}

// ---------------------------------------------------------------------------
// GEMM2 split-K8: g_zpart[kc] = wh[:, kc*64:+64] @ tanh(s+gh)[kc*64:+64, :]
// PRE-gridsync prologue (overlapped under GEMM1): stage A (wh) AND compute
// the 64 gh rows this block needs: sgh[r] = dot(wg[kbase+r,:], h).
// B = tanh(sum of 6 s-partials + sgh[row]) on the fly. Grid (6,3,8) = 144.
// ---------------------------------------------------------------------------
__global__ void __launch_bounds__(256) k_gemm2(const float* __restrict__ wh,
                                               const float* __restrict__ wg,
                                               const float* __restrict__ h) {
    constexpr int KS = 64;
    __shared__ float As[KS][132];
    __shared__ float Bs[KS][68];
    __shared__ float sgh[KS];

    const int tx = threadIdx.x;
    const int tn = tx & 15;
    const int tm = tx >> 4;
    const int bn = blockIdx.x, bm = blockIdx.y, kc = blockIdx.z;
    const int kbase = kc * KS;

    // gh prologue (independent of GEMM1): 4 threads per row, 64 rows
    {
        int r = tx >> 2, sub = tx & 3;
        const float4* wgr = (const float4*)(wg + (kbase + r) * SEQ);
        const float4* hr  = (const float4*)h;
        float p = 0.f;
        #pragma unroll
        for (int c = sub; c < 128; c += 4) {
            float4 a = wgr[c], b = hr[c];
            p += a.x * b.x + a.y * b.y + a.z * b.z + a.w * b.w;
        }
        p += __shfl_down_sync(0xffffffffu, p, 2, 4);
        p += __shfl_down_sync(0xffffffffu, p, 1, 4);
        if (sub == 0) sgh[r] = p;
    }

    // A tile: wh rows bm*128..+127, cols kbase..+63 (independent of GEMM1)
    {
        int m = tx >> 1, c0 = (tx & 1) * 32;
        const float* ap = wh + (bm * 128 + m) * EMB + kbase + c0;
        #pragma unroll
        for (int q = 0; q < 8; q++) {
            float4 a = *(const float4*)(ap + 4 * q);
            As[c0 + 4 * q + 0][m] = a.x; As[c0 + 4 * q + 1][m] = a.y;
            As[c0 + 4 * q + 2][m] = a.z; As[c0 + 4 * q + 3][m] = a.w;
        }
    }
    __syncthreads();   // publish sgh (and As) before B build reads sgh

    cudaGridDependencySynchronize();   // s-partials ready

    // B tile: rows kbase..+63, cols bn*64..+63 = tanh(sum of NP1 partials + gh)
    #pragma unroll
    for (int q = 0; q < 4; q++) {
        int e = tx + 256 * q;
        int k = e >> 4, n4 = (e & 15) * 4;
        int off = (kbase + k) * LL + bn * 64 + n4;
        float bias = sgh[k];
        float4 s = *(const float4*)&g_spart[0][off];
        #pragma unroll
        for (int p = 1; p < NP1; p++) {
            float4 t = *(const float4*)&g_spart[p][off];
            s.x += t.x; s.y += t.y; s.z += t.z; s.w += t.w;
        }
        float4 b;
        b.x = tanhf(s.x + bias); b.y = tanhf(s.y + bias);
        b.z = tanhf(s.z + bias); b.w = tanhf(s.w + bias);
        *(float4*)&Bs[k][n4] = b;
    }
    __syncthreads();

    float acc[8][4] = {};
    #pragma unroll 8
    for (int k = 0; k < KS; k++) {
        float4 a0 = *(const float4*)&As[k][tm * 8];
        float4 a1 = *(const float4*)&As[k][tm * 8 + 4];
        float4 b  = *(const float4*)&Bs[k][tn * 4];
        float av[8] = {a0.x, a0.y, a0.z, a0.w, a1.x, a1.y, a1.z, a1.w};
        float bv[4] = {b.x, b.y, b.z, b.w};
        #pragma unroll
        for (int i = 0; i < 8; i++)
            #pragma unroll
            for (int j = 0; j < 4; j++)
                acc[i][j] += av[i] * bv[j];
    }

    float* outp = g_zpart[kc];
    #pragma unroll
    for (int i = 0; i < 8; i++) {
        int m = bm * 128 + tm * 8 + i;
        float4 r;
        r.x = acc[i][0]; r.y = acc[i][1]; r.z = acc[i][2]; r.w = acc[i][3];
        *(float4*)&outp[m * LL + bn * 64 + tn * 4] = r;
    }
}

// ---------------------------------------------------------------------------
// Row softmax over z = sum of NP2 partials. One block per row, 96 threads,
// MLP=NP2 independent partial loads, 2-level (shuffle + 3-word) reduction.
// ---------------------------------------------------------------------------
__global__ void __launch_bounds__(96) k_softmax() {
    cudaGridDependencySynchronize();

    const int row = blockIdx.x;            // 0..383
    const int t = threadIdx.x;             // 0..95
    const int lane = t & 31, w = t >> 5;

    __shared__ float sred[3];
    __shared__ float ssum[3];

    const int idx = row * 96 + t;
    float4 x = ((const float4*)g_zpart[0])[idx];
    #pragma unroll
    for (int p = 1; p < NP2; p++) {
        float4 q = ((const float4*)g_zpart[p])[idx];
        x.x += q.x; x.y += q.y; x.z += q.z; x.w += q.w;
    }

    float m = fmaxf(fmaxf(x.x, x.y), fmaxf(x.z, x.w));
    #pragma unroll
    for (int o = 16; o; o >>= 1) m = fmaxf(m, __shfl_xor_sync(0xffffffffu, m, o));
    if (lane == 0) sred[w] = m;
    __syncthreads();
    m = fmaxf(fmaxf(sred[0], sred[1]), sred[2]);

    x.x = __expf(x.x - m); x.y = __expf(x.y - m);
    x.z = __expf(x.z - m); x.w = __expf(x.w - m);
    float s = (x.x + x.y) + (x.z + x.w);
    #pragma unroll
    for (int o = 16; o; o >>= 1) s += __shfl_xor_sync(0xffffffffu, s, o);
    if (lane == 0) ssum[w] = s;
    __syncthreads();
    float inv = 1.f / (ssum[0] + ssum[1] + ssum[2]);

    x.x *= inv; x.y *= inv; x.z *= inv; x.w *= inv;
    ((float4*)g_alpha)[idx] = x;
}

// ---------------------------------------------------------------------------
// out[i,j,k] = v[j,k] * alpha[i,j].  v loads issued BEFORE gridsync.
// At write roofline — unchanged from R9/R12.
// ---------------------------------------------------------------------------
__global__ void __launch_bounds__(384) k_out(const float* __restrict__ v,
                                             float4* __restrict__ out) {
    const int jb = blockIdx.x;    // 0..11
    const int ic = blockIdx.y;    // 0..23
    const int t  = threadIdx.x;   // 0..383

    const int g  = t / 96;
    const int k4 = t % 96;

    __shared__ float sa[16][32];

    float4 vv[8];
    #pragma unroll
    for (int jlo = 0; jlo < 8; jlo++)
        vv[jlo] = ((const float4*)v)[(jb * 32 + jlo * 4 + g) * 96 + k4];

    cudaGridDependencySynchronize();   // alpha ready

    #pragma unroll
    for (int idx = t; idx < 512; idx += 384) {
        int r = idx >> 5, c = idx & 31;
        sa[r][c] = g_alpha[(ic * 16 + r) * LL + jb * 32 + c];
    }
    __syncthreads();

    #pragma unroll 2
    for (int il = 0; il < 16; il++) {
        float4* o = out + ((size_t)(ic * 16 + il) * LL + jb * 32) * 96 + g * 96 + k4;
        #pragma unroll
        for (int jlo = 0; jlo < 8; jlo++) {
            float a = sa[il][jlo * 4 + g];
            float4 r;
            r.x = vv[jlo].x * a; r.y = vv[jlo].y * a;
            r.z = vv[jlo].z * a; r.w = vv[jlo].w * a;
            __stcs(o + jlo * 4 * 96, r);
        }
    }
}

// ---------------------------------------------------------------------------
template <typename F, typename... Args>
static void pdl_launch(F kern, dim3 g, dim3 b, Args... args) {
    cudaLaunchConfig_t cfg = {};
    cfg.gridDim = g; cfg.blockDim = b;
    cfg.dynamicSmemBytes = 0; cfg.stream = 0;
    cudaLaunchAttribute at;
    at.id = cudaLaunchAttributeProgrammaticStreamSerialization;
    at.val.programmaticStreamSerializationAllowed = 1;
    cfg.attrs = &at; cfg.numAttrs = 1;
    cudaLaunchKernelEx(&cfg, kern, args...);
}

extern "C" void kernel_launch(void* const* d_in, const int* in_sizes, int n_in,
                              void* d_out, int out_size) {
    const float* h  = (const float*)d_in[0];   // (512,1)
    const float* v  = (const float*)d_in[1];   // (384,384)
    const float* wh = (const float*)d_in[2];   // (384,512)
    const float* wv = (const float*)d_in[3];   // (512,384)
    const float* wg = (const float*)d_in[4];   // (512,512)

    // GEMM1: no dependencies, first kernel, plain launch.
    k_gemm1<<<dim3(LL / 64, EMB / 128, NP1), 256>>>(wv, v);

    // GEMM2: gh + wh staging overlapped under GEMM1 (pre-gridsync prologue).
    pdl_launch(k_gemm2, dim3(LL / 64, LL / 128, NP2), dim3(256), wh, wg, h);
    pdl_launch(k_softmax, dim3(LL), dim3(96));
    pdl_launch(k_out, dim3(12, 24), dim3(384), v, (float4*)d_out);

    (void)in_sizes; (void)n_in; (void)out_size;
}